// round 2
// baseline (speedup 1.0000x reference)
#include <cuda_runtime.h>
#include <cuda_bf16.h>
#include <cstdint>

#define N_NODES 100000
#define N_EDGES 1600000
#define EMB 64
#define HID 128
#define N_GRAPHS 512
#define N_TASKS 128
#define FULLMASK 0xffffffffu

// ---------------- device scratch (static, no allocation) ----------------
__device__ __align__(16) float g_x0[N_NODES * EMB];     // node features layer0 in
__device__ __align__(16) float g_agg0[N_NODES * EMB];   // scatter-add accumulator L0
__device__ __align__(16) float g_x1[N_NODES * HID];     // node features after layer0
__device__ __align__(16) float g_agg1[N_NODES * HID];   // scatter-add accumulator L1
__device__ __align__(16) float g_t0[16 * EMB];          // bond table layer0: bond_emb@we0+be0
__device__ __align__(16) float g_t1[16 * HID];          // bond table layer1
__device__ __align__(16) float g_pool[N_GRAPHS * HID];  // global_add_pool output

// ---------------- helpers ----------------
__device__ __forceinline__ void red_add_v4(float* p, float4 v) {
    asm volatile("red.global.add.v4.f32 [%0], {%1,%2,%3,%4};"
                 :: "l"(p), "f"(v.x), "f"(v.y), "f"(v.z), "f"(v.w) : "memory");
}

__device__ __forceinline__ float eluf(float x) { return x > 0.f ? x : expm1f(x); }

// ---------------- init: zero pool + compute both bond tables ----------------
__global__ void k_init(const float* __restrict__ bond_emb,
                       const float* __restrict__ we0, const float* __restrict__ be0,
                       const float* __restrict__ we1, const float* __restrict__ be1) {
    int tid = blockIdx.x * blockDim.x + threadIdx.x;
    int nth = gridDim.x * blockDim.x;
    for (int i = tid; i < N_GRAPHS * HID; i += nth) g_pool[i] = 0.f;
    for (int i = tid; i < 16 * EMB; i += nth) {
        int bt = i >> 6, o = i & 63;
        float acc = be0[o];
        #pragma unroll 8
        for (int k = 0; k < EMB; k++) acc += bond_emb[bt * EMB + k] * we0[k * EMB + o];
        g_t0[i] = acc;
    }
    for (int i = tid; i < 16 * HID; i += nth) {
        int bt = i >> 7, o = i & 127;
        float acc = be1[o];
        #pragma unroll 8
        for (int k = 0; k < EMB; k++) acc += bond_emb[bt * EMB + k] * we1[k * HID + o];
        g_t1[i] = acc;
    }
}

// ---------------- gather atom embeddings + zero agg0 ----------------
__global__ void k_gather(const int* __restrict__ x_idx, const float* __restrict__ atom_emb) {
    int tid = blockIdx.x * blockDim.x + threadIdx.x;
    int nth = gridDim.x * blockDim.x;
    const float4* ae = (const float4*)atom_emb;
    float4* x0 = (float4*)g_x0;
    float4* a0 = (float4*)g_agg0;
    const int NITEMS = N_NODES * (EMB / 4);
    for (int i = tid; i < NITEMS; i += nth) {
        int node = i >> 4;       // EMB/4 = 16 float4 per node
        int c = i & 15;
        int a = x_idx[node];
        x0[i] = ae[a * 16 + c];
        a0[i] = make_float4(0.f, 0.f, 0.f, 0.f);
    }
}

// ---------------- edge layer 0: msg = relu(x0[src] + t0[bond]) -> red into agg0 ----
// 2 edges per warp step (half-warps, float4 = 16 lanes * 4 floats = 64)
__global__ void k_edge0(const int* __restrict__ ei, const int* __restrict__ ea) {
    __shared__ float4 t0s[16 * 16];
    for (int i = threadIdx.x; i < 16 * 16; i += blockDim.x) t0s[i] = ((const float4*)g_t0)[i];
    __syncthreads();
    int lane = threadIdx.x & 31;
    int wid = (blockIdx.x * blockDim.x + threadIdx.x) >> 5;
    int nw = (gridDim.x * blockDim.x) >> 5;
    int half = lane >> 4, l16 = lane & 15;
    const int NB = N_EDGES / 32;   // 50000, exact
    const float4* x0 = (const float4*)g_x0;
    for (int b = wid; b < NB; b += nw) {
        int base = b * 32;
        int s_l = ei[base + lane];
        int d_l = ei[N_EDGES + base + lane];
        int t_l = ea[base + lane];
        #pragma unroll 4
        for (int j = 0; j < 16; j++) {
            int idx = 2 * j + half;
            int src = __shfl_sync(FULLMASK, s_l, idx);
            int dst = __shfl_sync(FULLMASK, d_l, idx);
            int bt  = __shfl_sync(FULLMASK, t_l, idx);
            float4 v = x0[src * 16 + l16];
            float4 t = t0s[bt * 16 + l16];
            float4 m;
            m.x = fmaxf(v.x + t.x, 0.f); m.y = fmaxf(v.y + t.y, 0.f);
            m.z = fmaxf(v.z + t.z, 0.f); m.w = fmaxf(v.w + t.w, 0.f);
            red_add_v4(g_agg0 + (size_t)dst * EMB + l16 * 4, m);
        }
    }
}

// ---------------- edge layer 1: msg = relu(x1[src] + t1[bond]) -> red into agg1 ----
// 1 edge per warp step (32 lanes * float4 = 128)
__global__ void k_edge1(const int* __restrict__ ei, const int* __restrict__ ea) {
    __shared__ float4 t1s[16 * 32];
    for (int i = threadIdx.x; i < 16 * 32; i += blockDim.x) t1s[i] = ((const float4*)g_t1)[i];
    __syncthreads();
    int lane = threadIdx.x & 31;
    int wid = (blockIdx.x * blockDim.x + threadIdx.x) >> 5;
    int nw = (gridDim.x * blockDim.x) >> 5;
    const int NB = N_EDGES / 32;
    const float4* x1 = (const float4*)g_x1;
    for (int b = wid; b < NB; b += nw) {
        int base = b * 32;
        int s_l = ei[base + lane];
        int d_l = ei[N_EDGES + base + lane];
        int t_l = ea[base + lane];
        #pragma unroll 4
        for (int j = 0; j < 32; j++) {
            int src = __shfl_sync(FULLMASK, s_l, j);
            int dst = __shfl_sync(FULLMASK, d_l, j);
            int bt  = __shfl_sync(FULLMASK, t_l, j);
            float4 v = x1[src * 32 + lane];
            float4 t = t1s[bt * 32 + lane];
            float4 m;
            m.x = fmaxf(v.x + t.x, 0.f); m.y = fmaxf(v.y + t.y, 0.f);
            m.z = fmaxf(v.z + t.z, 0.f); m.w = fmaxf(v.w + t.w, 0.f);
            red_add_v4(g_agg1 + (size_t)dst * HID + lane * 4, m);
        }
    }
}

// ---------------- node MLP layer 0: x1 = elu(elu((x0+agg0)@W1+b1)@W2+b2) ------
// 2 nodes per warp; weights in dynamic smem; also zeros agg1.
__global__ void k_mlp0(const float* __restrict__ w1, const float* __restrict__ b1,
                       const float* __restrict__ w2, const float* __restrict__ b2) {
    extern __shared__ float smem[];
    float* W1s = smem;                 // 64*128 = 8192
    float* W2s = smem + 8192;          // 128*128 = 16384
    float* b1s = smem + 24576;         // 128
    float* b2s = smem + 24704;         // 128
    float* bufs = smem + 24832;        // per warp: h0[64] h1[64] t0[128] t1[128] = 384
    for (int i = threadIdx.x; i < 8192; i += blockDim.x) W1s[i] = w1[i];
    for (int i = threadIdx.x; i < 16384; i += blockDim.x) W2s[i] = w2[i];
    if (threadIdx.x < 128) { b1s[threadIdx.x] = b1[threadIdx.x]; b2s[threadIdx.x] = b2[threadIdx.x]; }
    __syncthreads();
    int lane = threadIdx.x & 31, w = threadIdx.x >> 5;
    float* h_s = bufs + w * 384;
    float* t_s = h_s + 128;
    int wid = blockIdx.x * (blockDim.x >> 5) + w;
    int nw = gridDim.x * (blockDim.x >> 5);
    const int NP = N_NODES / 2;   // 50000, exact
    for (int p = wid; p < NP; p += nw) {
        int n0 = p * 2;
        {
            float2 a0 = *(const float2*)(g_x0 + (size_t)n0 * EMB + lane * 2);
            float2 g0 = *(const float2*)(g_agg0 + (size_t)n0 * EMB + lane * 2);
            float2 a1 = *(const float2*)(g_x0 + (size_t)(n0 + 1) * EMB + lane * 2);
            float2 g1 = *(const float2*)(g_agg0 + (size_t)(n0 + 1) * EMB + lane * 2);
            h_s[2 * lane] = a0.x + g0.x; h_s[2 * lane + 1] = a0.y + g0.y;
            h_s[64 + 2 * lane] = a1.x + g1.x; h_s[64 + 2 * lane + 1] = a1.y + g1.y;
        }
        __syncwarp();
        float4 acc0 = *(const float4*)(b1s + 4 * lane);
        float4 acc1 = acc0;
        #pragma unroll 8
        for (int k = 0; k < 64; k++) {
            float4 wv = *(const float4*)(W1s + k * 128 + 4 * lane);
            float h0 = h_s[k], h1 = h_s[64 + k];
            acc0.x += h0 * wv.x; acc0.y += h0 * wv.y; acc0.z += h0 * wv.z; acc0.w += h0 * wv.w;
            acc1.x += h1 * wv.x; acc1.y += h1 * wv.y; acc1.z += h1 * wv.z; acc1.w += h1 * wv.w;
        }
        float4 t0, t1;
        t0.x = eluf(acc0.x); t0.y = eluf(acc0.y); t0.z = eluf(acc0.z); t0.w = eluf(acc0.w);
        t1.x = eluf(acc1.x); t1.y = eluf(acc1.y); t1.z = eluf(acc1.z); t1.w = eluf(acc1.w);
        *(float4*)(t_s + 4 * lane) = t0;
        *(float4*)(t_s + 128 + 4 * lane) = t1;
        __syncwarp();
        acc0 = *(const float4*)(b2s + 4 * lane);
        acc1 = acc0;
        #pragma unroll 8
        for (int k = 0; k < 128; k++) {
            float4 wv = *(const float4*)(W2s + k * 128 + 4 * lane);
            float u0 = t_s[k], u1 = t_s[128 + k];
            acc0.x += u0 * wv.x; acc0.y += u0 * wv.y; acc0.z += u0 * wv.z; acc0.w += u0 * wv.w;
            acc1.x += u1 * wv.x; acc1.y += u1 * wv.y; acc1.z += u1 * wv.z; acc1.w += u1 * wv.w;
        }
        float4 o0, o1;
        o0.x = eluf(acc0.x); o0.y = eluf(acc0.y); o0.z = eluf(acc0.z); o0.w = eluf(acc0.w);
        o1.x = eluf(acc1.x); o1.y = eluf(acc1.y); o1.z = eluf(acc1.z); o1.w = eluf(acc1.w);
        *(float4*)(g_x1 + (size_t)n0 * HID + lane * 4) = o0;
        *(float4*)(g_x1 + (size_t)(n0 + 1) * HID + lane * 4) = o1;
        float4 z = make_float4(0.f, 0.f, 0.f, 0.f);
        *(float4*)(g_agg1 + (size_t)n0 * HID + lane * 4) = z;
        *(float4*)(g_agg1 + (size_t)(n0 + 1) * HID + lane * 4) = z;
        __syncwarp();
    }
}

// ---------------- node MLP layer 1 + fused global_add_pool ----------------
__global__ void k_mlp1(const float* __restrict__ w1, const float* __restrict__ b1,
                       const float* __restrict__ w2, const float* __restrict__ b2,
                       const int* __restrict__ batch) {
    extern __shared__ float smem[];
    float* W1s = smem;                 // 128*128 = 16384
    float* W2s = smem + 16384;         // 16384
    float* b1s = smem + 32768;
    float* b2s = smem + 32896;
    float* bufs = smem + 33024;        // per warp: h0 h1 (256) + t0 t1 (256) = 512
    for (int i = threadIdx.x; i < 16384; i += blockDim.x) W1s[i] = w1[i];
    for (int i = threadIdx.x; i < 16384; i += blockDim.x) W2s[i] = w2[i];
    if (threadIdx.x < 128) { b1s[threadIdx.x] = b1[threadIdx.x]; b2s[threadIdx.x] = b2[threadIdx.x]; }
    __syncthreads();
    int lane = threadIdx.x & 31, w = threadIdx.x >> 5;
    float* h_s = bufs + w * 512;
    float* t_s = h_s + 256;
    int wid = blockIdx.x * (blockDim.x >> 5) + w;
    int nw = gridDim.x * (blockDim.x >> 5);
    const int NP = N_NODES / 2;
    for (int p = wid; p < NP; p += nw) {
        int n0 = p * 2;
        {
            float4 a0 = *(const float4*)(g_x1 + (size_t)n0 * HID + lane * 4);
            float4 g0 = *(const float4*)(g_agg1 + (size_t)n0 * HID + lane * 4);
            float4 a1 = *(const float4*)(g_x1 + (size_t)(n0 + 1) * HID + lane * 4);
            float4 g1 = *(const float4*)(g_agg1 + (size_t)(n0 + 1) * HID + lane * 4);
            float4 s0 = make_float4(a0.x + g0.x, a0.y + g0.y, a0.z + g0.z, a0.w + g0.w);
            float4 s1 = make_float4(a1.x + g1.x, a1.y + g1.y, a1.z + g1.z, a1.w + g1.w);
            *(float4*)(h_s + 4 * lane) = s0;
            *(float4*)(h_s + 128 + 4 * lane) = s1;
        }
        __syncwarp();
        float4 acc0 = *(const float4*)(b1s + 4 * lane);
        float4 acc1 = acc0;
        #pragma unroll 8
        for (int k = 0; k < 128; k++) {
            float4 wv = *(const float4*)(W1s + k * 128 + 4 * lane);
            float h0 = h_s[k], h1 = h_s[128 + k];
            acc0.x += h0 * wv.x; acc0.y += h0 * wv.y; acc0.z += h0 * wv.z; acc0.w += h0 * wv.w;
            acc1.x += h1 * wv.x; acc1.y += h1 * wv.y; acc1.z += h1 * wv.z; acc1.w += h1 * wv.w;
        }
        float4 t0, t1;
        t0.x = eluf(acc0.x); t0.y = eluf(acc0.y); t0.z = eluf(acc0.z); t0.w = eluf(acc0.w);
        t1.x = eluf(acc1.x); t1.y = eluf(acc1.y); t1.z = eluf(acc1.z); t1.w = eluf(acc1.w);
        *(float4*)(t_s + 4 * lane) = t0;
        *(float4*)(t_s + 128 + 4 * lane) = t1;
        __syncwarp();
        acc0 = *(const float4*)(b2s + 4 * lane);
        acc1 = acc0;
        #pragma unroll 8
        for (int k = 0; k < 128; k++) {
            float4 wv = *(const float4*)(W2s + k * 128 + 4 * lane);
            float u0 = t_s[k], u1 = t_s[128 + k];
            acc0.x += u0 * wv.x; acc0.y += u0 * wv.y; acc0.z += u0 * wv.z; acc0.w += u0 * wv.w;
            acc1.x += u1 * wv.x; acc1.y += u1 * wv.y; acc1.z += u1 * wv.z; acc1.w += u1 * wv.w;
        }
        float4 o0, o1;
        o0.x = eluf(acc0.x); o0.y = eluf(acc0.y); o0.z = eluf(acc0.z); o0.w = eluf(acc0.w);
        o1.x = eluf(acc1.x); o1.y = eluf(acc1.y); o1.z = eluf(acc1.z); o1.w = eluf(acc1.w);
        // fused global_add_pool: x2 never hits DRAM
        int bg0 = batch[n0], bg1 = batch[n0 + 1];
        red_add_v4(g_pool + (size_t)bg0 * HID + lane * 4, o0);
        red_add_v4(g_pool + (size_t)bg1 * HID + lane * 4, o1);
        __syncwarp();
    }
}

// ---------------- head: out = relu(pool@lin1+b)@lin2+b ----------------
__global__ void k_head(const float* __restrict__ w1, const float* __restrict__ b1,
                       const float* __restrict__ w2, const float* __restrict__ b2,
                       float* __restrict__ out) {
    __shared__ float p_s[HID], h_s[HID];
    int g = blockIdx.x, t = threadIdx.x;
    p_s[t] = g_pool[g * HID + t];
    __syncthreads();
    float acc = b1[t];
    #pragma unroll 8
    for (int k = 0; k < HID; k++) acc += p_s[k] * w1[k * N_TASKS + t];
    h_s[t] = fmaxf(acc, 0.f);
    __syncthreads();
    acc = b2[t];
    #pragma unroll 8
    for (int k = 0; k < HID; k++) acc += h_s[k] * w2[k * N_TASKS + t];
    out[g * N_TASKS + t] = acc;
}

// ---------------- launch ----------------
extern "C" void kernel_launch(void* const* d_in, const int* in_sizes, int n_in,
                              void* d_out, int out_size) {
    const int*   x_idx    = (const int*)  d_in[0];
    const int*   ei       = (const int*)  d_in[1];
    const int*   ea       = (const int*)  d_in[2];
    const int*   batch    = (const int*)  d_in[3];
    const float* atom_emb = (const float*)d_in[4];
    const float* bond_emb = (const float*)d_in[5];
    const float* we0      = (const float*)d_in[6];
    const float* be0      = (const float*)d_in[7];
    const float* w1_0     = (const float*)d_in[8];
    const float* b1_0     = (const float*)d_in[9];
    const float* w2_0     = (const float*)d_in[10];
    const float* b2_0     = (const float*)d_in[11];
    const float* we1      = (const float*)d_in[12];
    const float* be1      = (const float*)d_in[13];
    const float* w1_1     = (const float*)d_in[14];
    const float* b1_1     = (const float*)d_in[15];
    const float* w2_1     = (const float*)d_in[16];
    const float* b2_1     = (const float*)d_in[17];
    const float* lin1_w   = (const float*)d_in[18];
    const float* lin1_b   = (const float*)d_in[19];
    const float* lin2_w   = (const float*)d_in[20];
    const float* lin2_b   = (const float*)d_in[21];
    float* out = (float*)d_out;

    size_t smem0 = (size_t)(24832 + 16 * 384) * sizeof(float);   // 123,904 B
    size_t smem1 = (size_t)(33024 + 16 * 512) * sizeof(float);   // 164,864 B
    cudaFuncSetAttribute(k_mlp0, cudaFuncAttributeMaxDynamicSharedMemorySize, (int)smem0);
    cudaFuncSetAttribute(k_mlp1, cudaFuncAttributeMaxDynamicSharedMemorySize, (int)smem1);

    k_init  <<<32, 256>>>(bond_emb, we0, be0, we1, be1);
    k_gather<<<2048, 256>>>(x_idx, atom_emb);
    k_edge0 <<<1480, 256>>>(ei, ea);
    k_mlp0  <<<296, 512, smem0>>>(w1_0, b1_0, w2_0, b2_0);
    k_edge1 <<<1480, 256>>>(ei, ea);
    k_mlp1  <<<296, 512, smem1>>>(w1_1, b1_1, w2_1, b2_1, batch);
    k_head  <<<512, 128>>>(lin1_w, lin1_b, lin2_w, lin2_b, out);
}

// round 5
// speedup vs baseline: 1.5511x; 1.5511x over previous
#include <cuda_runtime.h>
#include <cuda_bf16.h>
#include <cstdint>

#define N_NODES 100000
#define N_EDGES 1600000
#define EMB 64
#define HID 128
#define N_GRAPHS 512
#define N_TASKS 128
#define FULLMASK 0xffffffffu

// ---------------- device scratch (static, no allocation) ----------------
__device__ __align__(16) float g_x0[N_NODES * EMB];
__device__ __align__(16) float g_agg0[N_NODES * EMB];
__device__ __align__(16) float g_x1[N_NODES * HID];
__device__ __align__(16) float g_agg1[N_NODES * HID];
__device__ __align__(16) float g_t0[16 * EMB];
__device__ __align__(16) float g_t1[16 * HID];
__device__ __align__(16) float g_pool[N_GRAPHS * HID];
// bf16 hi/lo split weights, pre-swizzled to match smem layout exactly:
// layer0: [W1hi 16384 | W1lo 16384 | W2hi 32768 | W2lo 32768]
// layer1: [W1hi 32768 | W1lo 32768 | W2hi 32768 | W2lo 32768]
__device__ __align__(16) unsigned char g_wb0[98304];
__device__ __align__(16) unsigned char g_wb1[131072];

// ---------------- helpers ----------------
__device__ __forceinline__ void red_add_v4(float* p, float4 v) {
    asm volatile("red.global.add.v4.f32 [%0], {%1,%2,%3,%4};"
                 :: "l"(p), "f"(v.x), "f"(v.y), "f"(v.z), "f"(v.w) : "memory");
}
__device__ __forceinline__ void red_add_v2(float* p, float a, float b) {
    asm volatile("red.global.add.v2.f32 [%0], {%1,%2};"
                 :: "l"(p), "f"(a), "f"(b) : "memory");
}
__device__ __forceinline__ float elu_fast(float x) { return x > 0.f ? x : (__expf(x) - 1.f); }
__device__ __forceinline__ uint32_t pack2(float a, float b) {
    __nv_bfloat162 h = __floats2bfloat162_rn(a, b);
    return *(uint32_t*)&h;
}
__device__ __forceinline__ uint32_t smem_u32(const void* p) {
    uint32_t a;
    asm("{ .reg .u64 t; cvta.to.shared.u64 t, %1; cvt.u32.u64 %0, t; }" : "=r"(a) : "l"(p));
    return a;
}
// swizzled byte offset within a [row][col] bf16 tile; rowb bytes per row.
// 16B chunks XOR-permuted by (row&7) -> conflict-free ldmatrix + staging.
__device__ __forceinline__ uint32_t swz(int r, int c, int rowb) {
    return (uint32_t)(r * rowb + ((((c >> 3) ^ (r & 7))) << 4) + (c & 7) * 2);
}
__device__ __forceinline__ void ldsm_x4(uint32_t a[4], uint32_t addr) {
    asm volatile("ldmatrix.sync.aligned.m8n8.x4.shared.b16 {%0,%1,%2,%3}, [%4];"
                 : "=r"(a[0]), "=r"(a[1]), "=r"(a[2]), "=r"(a[3]) : "r"(addr));
}
__device__ __forceinline__ void ldsm_x4_t(uint32_t a[4], uint32_t addr) {
    asm volatile("ldmatrix.sync.aligned.m8n8.x4.trans.shared.b16 {%0,%1,%2,%3}, [%4];"
                 : "=r"(a[0]), "=r"(a[1]), "=r"(a[2]), "=r"(a[3]) : "r"(addr));
}
__device__ __forceinline__ void mma_bf16(float d[4], const uint32_t a[4], uint32_t b0, uint32_t b1) {
    asm volatile("mma.sync.aligned.m16n8k16.row.col.f32.bf16.bf16.f32 "
                 "{%0,%1,%2,%3}, {%4,%5,%6,%7}, {%8,%9}, {%0,%1,%2,%3};"
                 : "+f"(d[0]), "+f"(d[1]), "+f"(d[2]), "+f"(d[3])
                 : "r"(a[0]), "r"(a[1]), "r"(a[2]), "r"(a[3]), "r"(b0), "r"(b1));
}

// ---------------- init: pool zero + bond tables + weight split blobs ----------------
__device__ __forceinline__ void split_store(unsigned char* hi, unsigned char* lo,
                                            uint32_t off, float w) {
    __nv_bfloat16 wh = __float2bfloat16_rn(w);
    __nv_bfloat16 wl = __float2bfloat16_rn(w - __bfloat162float(wh));
    *(__nv_bfloat16*)(hi + off) = wh;
    *(__nv_bfloat16*)(lo + off) = wl;
}

__global__ void k_init(const float* __restrict__ bond_emb,
                       const float* __restrict__ we0, const float* __restrict__ be0,
                       const float* __restrict__ we1, const float* __restrict__ be1,
                       const float* __restrict__ w1_0, const float* __restrict__ w2_0,
                       const float* __restrict__ w1_1, const float* __restrict__ w2_1) {
    int tid = blockIdx.x * blockDim.x + threadIdx.x;
    int nth = gridDim.x * blockDim.x;
    for (int i = tid; i < N_GRAPHS * HID; i += nth) g_pool[i] = 0.f;
    for (int i = tid; i < 16 * EMB; i += nth) {
        int bt = i >> 6, o = i & 63;
        float acc = be0[o];
        #pragma unroll 8
        for (int k = 0; k < EMB; k++) acc += bond_emb[bt * EMB + k] * we0[k * EMB + o];
        g_t0[i] = acc;
    }
    for (int i = tid; i < 16 * HID; i += nth) {
        int bt = i >> 7, o = i & 127;
        float acc = be1[o];
        #pragma unroll 8
        for (int k = 0; k < EMB; k++) acc += bond_emb[bt * EMB + k] * we1[k * HID + o];
        g_t1[i] = acc;
    }
    // weights as [k][n] bf16, 256B rows, swizzled
    for (int i = tid; i < 64 * 128; i += nth) {          // L0 W1
        int k = i >> 7, n = i & 127;
        split_store(g_wb0, g_wb0 + 16384, swz(k, n, 256), w1_0[i]);
    }
    for (int i = tid; i < 128 * 128; i += nth) {         // L0 W2
        int k = i >> 7, n = i & 127;
        split_store(g_wb0 + 32768, g_wb0 + 65536, swz(k, n, 256), w2_0[i]);
    }
    for (int i = tid; i < 128 * 128; i += nth) {         // L1 W1
        int k = i >> 7, n = i & 127;
        split_store(g_wb1, g_wb1 + 32768, swz(k, n, 256), w1_1[i]);
    }
    for (int i = tid; i < 128 * 128; i += nth) {         // L1 W2
        int k = i >> 7, n = i & 127;
        split_store(g_wb1 + 65536, g_wb1 + 98304, swz(k, n, 256), w2_1[i]);
    }
}

// ---------------- gather + zero agg0 ----------------
__global__ void k_gather(const int* __restrict__ x_idx, const float* __restrict__ atom_emb) {
    int tid = blockIdx.x * blockDim.x + threadIdx.x;
    int nth = gridDim.x * blockDim.x;
    const float4* ae = (const float4*)atom_emb;
    float4* x0 = (float4*)g_x0;
    float4* a0 = (float4*)g_agg0;
    const int NITEMS = N_NODES * (EMB / 4);
    for (int i = tid; i < NITEMS; i += nth) {
        int node = i >> 4;
        int c = i & 15;
        int a = x_idx[node];
        x0[i] = ae[a * 16 + c];
        a0[i] = make_float4(0.f, 0.f, 0.f, 0.f);
    }
}

// ---------------- edge layer 0 ----------------
__global__ void k_edge0(const int* __restrict__ ei, const int* __restrict__ ea) {
    __shared__ float4 t0s[16 * 16];
    for (int i = threadIdx.x; i < 16 * 16; i += blockDim.x) t0s[i] = ((const float4*)g_t0)[i];
    __syncthreads();
    int lane = threadIdx.x & 31;
    int wid = (blockIdx.x * blockDim.x + threadIdx.x) >> 5;
    int nw = (gridDim.x * blockDim.x) >> 5;
    int half = lane >> 4, l16 = lane & 15;
    const int NB = N_EDGES / 32;
    const float4* x0 = (const float4*)g_x0;
    for (int b = wid; b < NB; b += nw) {
        int base = b * 32;
        int s_l = ei[base + lane];
        int d_l = ei[N_EDGES + base + lane];
        int t_l = ea[base + lane];
        #pragma unroll 4
        for (int j = 0; j < 16; j++) {
            int idx = 2 * j + half;
            int src = __shfl_sync(FULLMASK, s_l, idx);
            int dst = __shfl_sync(FULLMASK, d_l, idx);
            int bt  = __shfl_sync(FULLMASK, t_l, idx);
            float4 v = x0[src * 16 + l16];
            float4 t = t0s[bt * 16 + l16];
            float4 m;
            m.x = fmaxf(v.x + t.x, 0.f); m.y = fmaxf(v.y + t.y, 0.f);
            m.z = fmaxf(v.z + t.z, 0.f); m.w = fmaxf(v.w + t.w, 0.f);
            red_add_v4(g_agg0 + (size_t)dst * EMB + l16 * 4, m);
        }
    }
}

// ---------------- edge layer 1 ----------------
__global__ void k_edge1(const int* __restrict__ ei, const int* __restrict__ ea) {
    __shared__ float4 t1s[16 * 32];
    for (int i = threadIdx.x; i < 16 * 32; i += blockDim.x) t1s[i] = ((const float4*)g_t1)[i];
    __syncthreads();
    int lane = threadIdx.x & 31;
    int wid = (blockIdx.x * blockDim.x + threadIdx.x) >> 5;
    int nw = (gridDim.x * blockDim.x) >> 5;
    const int NB = N_EDGES / 32;
    const float4* x1 = (const float4*)g_x1;
    for (int b = wid; b < NB; b += nw) {
        int base = b * 32;
        int s_l = ei[base + lane];
        int d_l = ei[N_EDGES + base + lane];
        int t_l = ea[base + lane];
        #pragma unroll 4
        for (int j = 0; j < 32; j++) {
            int src = __shfl_sync(FULLMASK, s_l, j);
            int dst = __shfl_sync(FULLMASK, d_l, j);
            int bt  = __shfl_sync(FULLMASK, t_l, j);
            float4 v = x1[src * 32 + lane];
            float4 t = t1s[bt * 32 + lane];
            float4 m;
            m.x = fmaxf(v.x + t.x, 0.f); m.y = fmaxf(v.y + t.y, 0.f);
            m.z = fmaxf(v.z + t.z, 0.f); m.w = fmaxf(v.w + t.w, 0.f);
            red_add_v4(g_agg1 + (size_t)dst * HID + lane * 4, m);
        }
    }
}

// ============ GINE MLP on HMMA (mma.sync m16n8k16 bf16) ============
// Per 128-node tile: D[128,128] = A @ W. Weights hi/lo bf16 (2 products with
// Ahi kills systematic weight-rounding bias); activations single bf16 (random
// rounding, attenuated by the 512-graph pooling). 8 warps: each m32 x n64.
template<int K1, bool L1>
__global__ void __launch_bounds__(256, 1)
k_mlp_mma(const float* __restrict__ b1, const float* __restrict__ b2,
          const int* __restrict__ batch) {
    extern __shared__ char smem[];
    constexpr int W1B = K1 * 256;            // W1 buffer bytes (K1 rows x 128 n x 2B)
    constexpr int W2B = 128 * 256;           // 32768
    constexpr int RB1 = K1 * 2;              // As row bytes
    constexpr int ASB = 128 * RB1;
    constexpr int AS2B = 128 * 256;
    constexpr int BLOB = 2 * W1B + 2 * W2B;
    char* W1hi = smem;
    char* W1lo = smem + W1B;
    char* W2hi = smem + 2 * W1B;
    char* W2lo = smem + 2 * W1B + W2B;
    char* Asb  = smem + BLOB;
    char* As2b = Asb + ASB;
    float* b1s = (float*)(As2b + AS2B);
    float* b2s = b1s + 128;

    const float* xin   = L1 ? g_x1 : g_x0;
    const float* aggin = L1 ? g_agg1 : g_agg0;
    const unsigned char* blob = L1 ? g_wb1 : g_wb0;

    int tid = threadIdx.x;
    // copy pre-swizzled weight blob (byte-identical layout)
    {
        const uint4* src = (const uint4*)blob;
        uint4* dst = (uint4*)smem;
        for (int i = tid; i < BLOB / 16; i += 256) dst[i] = src[i];
    }
    if (tid < 128) { b1s[tid] = b1[tid]; b2s[tid] = b2[tid]; }

    uint32_t As_u  = smem_u32(Asb);
    uint32_t As2_u = smem_u32(As2b);
    uint32_t W1hi_u = smem_u32(W1hi), W1lo_u = smem_u32(W1lo);
    uint32_t W2hi_u = smem_u32(W2hi), W2lo_u = smem_u32(W2lo);

    int lane = tid & 31, wq = tid >> 5;
    int mbase = (wq & 3) * 32;               // 32 rows per warp
    int nbase = (wq >> 2) * 64;              // 64 cols per warp
    int g = lane >> 3, lr = lane & 7;
    int fr = (g & 1) * 8 + lr;               // ldmatrix lane row-in-frag
    int fc8 = (g >> 1) * 8;                  // ldmatrix lane col-offset
    int qr = lane >> 2, qp = lane & 3;       // D-frag row/colpair

    const int NT = (N_NODES + 127) / 128;    // 782
    __syncthreads();

    for (int tile = blockIdx.x; tile < NT; tile += gridDim.x) {
        // ---- stage As: bf16(x + agg), swizzled ----
        {
            int r = tid >> 1;
            int node = tile * 128 + r;
            int kh = (tid & 1) * (K1 / 2);
            char* rowp = Asb + r * RB1;
            if (node < N_NODES) {
                const float4* xp = (const float4*)(xin + (size_t)node * K1);
                const float4* ap = (const float4*)(aggin + (size_t)node * K1);
                #pragma unroll
                for (int c = 0; c < K1 / 16; c++) {
                    int kk = kh + c * 8;
                    float4 u0 = xp[kk / 4], v0 = ap[kk / 4];
                    float4 u1 = xp[kk / 4 + 1], v1 = ap[kk / 4 + 1];
                    uint4 pk;
                    pk.x = pack2(u0.x + v0.x, u0.y + v0.y);
                    pk.y = pack2(u0.z + v0.z, u0.w + v0.w);
                    pk.z = pack2(u1.x + v1.x, u1.y + v1.y);
                    pk.w = pack2(u1.z + v1.z, u1.w + v1.w);
                    *(uint4*)(rowp + ((((kk >> 3) ^ (r & 7))) << 4)) = pk;
                }
            } else {
                uint4 z = make_uint4(0u, 0u, 0u, 0u);
                #pragma unroll
                for (int c = 0; c < K1 / 16; c++) {
                    int kk = kh + c * 8;
                    *(uint4*)(rowp + ((((kk >> 3) ^ (r & 7))) << 4)) = z;
                }
            }
        }
        __syncthreads();

        float d0[8][4], d1[8][4];
        #pragma unroll
        for (int i = 0; i < 8; i++)
            #pragma unroll
            for (int j = 0; j < 4; j++) { d0[i][j] = 0.f; d1[i][j] = 0.f; }

        // ---- GEMM1: A[128xK1] @ W1 ----
        #pragma unroll
        for (int ks = 0; ks < K1 / 16; ks++) {
            uint32_t a0[4], a1[4];
            ldsm_x4(a0, As_u + swz(mbase + fr, ks * 16 + fc8, RB1));
            ldsm_x4(a1, As_u + swz(mbase + 16 + fr, ks * 16 + fc8, RB1));
            #pragma unroll
            for (int np = 0; np < 4; np++) {
                uint32_t woff = swz(ks * 16 + fr, nbase + np * 16 + fc8, 256);
                uint32_t bh[4], bl[4];
                ldsm_x4_t(bh, W1hi_u + woff);
                mma_bf16(d0[2 * np], a0, bh[0], bh[1]); mma_bf16(d0[2 * np + 1], a0, bh[2], bh[3]);
                mma_bf16(d1[2 * np], a1, bh[0], bh[1]); mma_bf16(d1[2 * np + 1], a1, bh[2], bh[3]);
                ldsm_x4_t(bl, W1lo_u + woff);
                mma_bf16(d0[2 * np], a0, bl[0], bl[1]); mma_bf16(d0[2 * np + 1], a0, bl[2], bl[3]);
                mma_bf16(d1[2 * np], a1, bl[0], bl[1]); mma_bf16(d1[2 * np + 1], a1, bl[2], bl[3]);
            }
        }

        // ---- epilogue1: t = elu(D + b1) -> As2 (bf16, swizzled) ----
        #pragma unroll
        for (int i = 0; i < 8; i++) {
            int n = nbase + i * 8 + qp * 2;
            float bb0 = b1s[n], bb1 = b1s[n + 1];
            *(uint32_t*)(As2b + swz(mbase + qr,      n, 256)) = pack2(elu_fast(d0[i][0] + bb0), elu_fast(d0[i][1] + bb1));
            *(uint32_t*)(As2b + swz(mbase + qr + 8,  n, 256)) = pack2(elu_fast(d0[i][2] + bb0), elu_fast(d0[i][3] + bb1));
            *(uint32_t*)(As2b + swz(mbase + qr + 16, n, 256)) = pack2(elu_fast(d1[i][0] + bb0), elu_fast(d1[i][1] + bb1));
            *(uint32_t*)(As2b + swz(mbase + qr + 24, n, 256)) = pack2(elu_fast(d1[i][2] + bb0), elu_fast(d1[i][3] + bb1));
        }
        __syncthreads();

        #pragma unroll
        for (int i = 0; i < 8; i++)
            #pragma unroll
            for (int j = 0; j < 4; j++) { d0[i][j] = 0.f; d1[i][j] = 0.f; }

        // ---- GEMM2: t[128x128] @ W2 ----
        #pragma unroll
        for (int ks = 0; ks < 8; ks++) {
            uint32_t a0[4], a1[4];
            ldsm_x4(a0, As2_u + swz(mbase + fr, ks * 16 + fc8, 256));
            ldsm_x4(a1, As2_u + swz(mbase + 16 + fr, ks * 16 + fc8, 256));
            #pragma unroll
            for (int np = 0; np < 4; np++) {
                uint32_t woff = swz(ks * 16 + fr, nbase + np * 16 + fc8, 256);
                uint32_t bh[4], bl[4];
                ldsm_x4_t(bh, W2hi_u + woff);
                mma_bf16(d0[2 * np], a0, bh[0], bh[1]); mma_bf16(d0[2 * np + 1], a0, bh[2], bh[3]);
                mma_bf16(d1[2 * np], a1, bh[0], bh[1]); mma_bf16(d1[2 * np + 1], a1, bh[2], bh[3]);
                ldsm_x4_t(bl, W2lo_u + woff);
                mma_bf16(d0[2 * np], a0, bl[0], bl[1]); mma_bf16(d0[2 * np + 1], a0, bl[2], bl[3]);
                mma_bf16(d1[2 * np], a1, bl[0], bl[1]); mma_bf16(d1[2 * np + 1], a1, bl[2], bl[3]);
            }
        }

        // ---- epilogue2 ----
        int r0 = mbase + qr;
        if constexpr (!L1) {
            #pragma unroll
            for (int f = 0; f < 4; f++) {
                int row = r0 + f * 8;
                int node = tile * 128 + row;
                if (node < N_NODES) {
                    float* xo = g_x1 + (size_t)node * HID;
                    float* ao = g_agg1 + (size_t)node * HID;
                    #pragma unroll
                    for (int i = 0; i < 8; i++) {
                        int n = nbase + i * 8 + qp * 2;
                        float e0, e1;
                        if (f < 2) { e0 = d0[i][2 * f] ; e1 = d0[i][2 * f + 1]; }
                        else       { e0 = d1[i][2 * (f - 2)]; e1 = d1[i][2 * (f - 2) + 1]; }
                        float2 o = make_float2(elu_fast(e0 + b2s[n]), elu_fast(e1 + b2s[n + 1]));
                        *(float2*)(xo + n) = o;
                        *(float2*)(ao + n) = make_float2(0.f, 0.f);
                    }
                }
            }
        } else {
            #pragma unroll
            for (int f = 0; f < 4; f++) {
                int row = r0 + f * 8;
                int node = tile * 128 + row;
                if (node < N_NODES) {
                    int gg = batch[node];
                    float* pp = g_pool + (size_t)gg * HID;
                    #pragma unroll
                    for (int i = 0; i < 8; i++) {
                        int n = nbase + i * 8 + qp * 2;
                        float e0, e1;
                        if (f < 2) { e0 = d0[i][2 * f]; e1 = d0[i][2 * f + 1]; }
                        else       { e0 = d1[i][2 * (f - 2)]; e1 = d1[i][2 * (f - 2) + 1]; }
                        red_add_v2(pp + n, elu_fast(e0 + b2s[n]), elu_fast(e1 + b2s[n + 1]));
                    }
                }
            }
        }
        __syncthreads();
    }
}

// ---------------- head ----------------
__global__ void k_head(const float* __restrict__ w1, const float* __restrict__ b1,
                       const float* __restrict__ w2, const float* __restrict__ b2,
                       float* __restrict__ out) {
    __shared__ float p_s[HID], h_s[HID];
    int g = blockIdx.x, t = threadIdx.x;
    p_s[t] = g_pool[g * HID + t];
    __syncthreads();
    float acc = b1[t];
    #pragma unroll 8
    for (int k = 0; k < HID; k++) acc += p_s[k] * w1[k * N_TASKS + t];
    h_s[t] = fmaxf(acc, 0.f);
    __syncthreads();
    acc = b2[t];
    #pragma unroll 8
    for (int k = 0; k < HID; k++) acc += h_s[k] * w2[k * N_TASKS + t];
    out[g * N_TASKS + t] = acc;
}

// ---------------- launch ----------------
extern "C" void kernel_launch(void* const* d_in, const int* in_sizes, int n_in,
                              void* d_out, int out_size) {
    const int*   x_idx    = (const int*)  d_in[0];
    const int*   ei       = (const int*)  d_in[1];
    const int*   ea       = (const int*)  d_in[2];
    const int*   batch    = (const int*)  d_in[3];
    const float* atom_emb = (const float*)d_in[4];
    const float* bond_emb = (const float*)d_in[5];
    const float* we0      = (const float*)d_in[6];
    const float* be0      = (const float*)d_in[7];
    const float* w1_0     = (const float*)d_in[8];
    const float* b1_0     = (const float*)d_in[9];
    const float* w2_0     = (const float*)d_in[10];
    const float* b2_0     = (const float*)d_in[11];
    const float* we1      = (const float*)d_in[12];
    const float* be1      = (const float*)d_in[13];
    const float* w1_1     = (const float*)d_in[14];
    const float* b1_1     = (const float*)d_in[15];
    const float* w2_1     = (const float*)d_in[16];
    const float* b2_1     = (const float*)d_in[17];
    const float* lin1_w   = (const float*)d_in[18];
    const float* lin1_b   = (const float*)d_in[19];
    const float* lin2_w   = (const float*)d_in[20];
    const float* lin2_b   = (const float*)d_in[21];
    float* out = (float*)d_out;

    // smem: weights blob + As + As2 + biases
    int smem0 = 98304  + 16384 + 32768 + 1024;   // 148480
    int smem1 = 131072 + 32768 + 32768 + 1024;   // 197632
    cudaFuncSetAttribute(k_mlp_mma<64, false>, cudaFuncAttributeMaxDynamicSharedMemorySize, smem0);
    cudaFuncSetAttribute(k_mlp_mma<128, true>, cudaFuncAttributeMaxDynamicSharedMemorySize, smem1);

    k_init  <<<128, 256>>>(bond_emb, we0, be0, we1, be1, w1_0, w2_0, w1_1, w2_1);
    k_gather<<<2048, 256>>>(x_idx, atom_emb);
    k_edge0 <<<1480, 256>>>(ei, ea);
    k_mlp_mma<64, false><<<148, 256, smem0>>>(b1_0, b2_0, batch);
    k_edge1 <<<1480, 256>>>(ei, ea);
    k_mlp_mma<128, true><<<148, 256, smem1>>>(b1_1, b2_1, batch);
    k_head  <<<512, 128>>>(lin1_w, lin1_b, lin2_w, lin2_b, out);
}

// round 6
// speedup vs baseline: 2.3487x; 1.5142x over previous
#include <cuda_runtime.h>
#include <cuda_bf16.h>
#include <cuda_fp16.h>
#include <cstdint>

#define N_NODES 100000
#define N_EDGES 1600000
#define EMB 64
#define HID 128
#define N_GRAPHS 512
#define N_TASKS 128
#define FULLMASK 0xffffffffu

// ---------------- device scratch (static, no allocation) ----------------
// fp16 node features / aggregators (halves edge-phase L2 traffic)
__device__ __align__(16) uint4 g_x0h[N_NODES * 8];     // 64 halves per node
__device__ __align__(16) uint4 g_agg0h[N_NODES * 8];
__device__ __align__(16) uint4 g_x1h[N_NODES * 16];    // 128 halves per node
__device__ __align__(16) uint4 g_agg1h[N_NODES * 16];
__device__ __align__(16) uint4 g_t0h[16 * 8];          // bond table L0 (fp16)
__device__ __align__(16) uint4 g_t1h[16 * 16];         // bond table L1 (fp16)
__device__ __align__(16) float g_pool[N_GRAPHS * HID];
// bf16 hi/lo split weights, pre-swizzled to match smem layout exactly
__device__ __align__(16) unsigned char g_wb0[98304];
__device__ __align__(16) unsigned char g_wb1[131072];

// ---------------- helpers ----------------
__device__ __forceinline__ void red_add_v2(float* p, float a, float b) {
    asm volatile("red.global.add.v2.f32 [%0], {%1,%2};"
                 :: "l"(p), "f"(a), "f"(b) : "memory");
}
__device__ __forceinline__ void red_add_f16x8(uint4* p, uint4 v) {
    asm volatile("red.global.add.noftz.v4.f16x2 [%0], {%1,%2,%3,%4};"
                 :: "l"(p), "r"(v.x), "r"(v.y), "r"(v.z), "r"(v.w) : "memory");
}
__device__ __forceinline__ float elu_fast(float x) { return x > 0.f ? x : (__expf(x) - 1.f); }
__device__ __forceinline__ uint32_t pack2(float a, float b) {
    __nv_bfloat162 h = __floats2bfloat162_rn(a, b);
    return *(uint32_t*)&h;
}
__device__ __forceinline__ uint32_t smem_u32(const void* p) {
    uint32_t a;
    asm("{ .reg .u64 t; cvta.to.shared.u64 t, %1; cvt.u32.u64 %0, t; }" : "=r"(a) : "l"(p));
    return a;
}
// half2 relu(a+b)
__device__ __forceinline__ uint32_t h2ra(uint32_t a, uint32_t b) {
    __half2 s = __hadd2(*(__half2*)&a, *(__half2*)&b);
    __half2 z = __float2half2_rn(0.f);
    s = __hmax2(s, z);
    return *(uint32_t*)&s;
}
__device__ __forceinline__ uint4 msg4(uint4 v, uint4 t) {
    uint4 m;
    m.x = h2ra(v.x, t.x); m.y = h2ra(v.y, t.y);
    m.z = h2ra(v.z, t.z); m.w = h2ra(v.w, t.w);
    return m;
}
// fp16 x + fp16 agg -> bf16 packed (8 dims)
__device__ __forceinline__ uint4 sum_pack_bf16(uint4 xv, uint4 av) {
    uint4 o;
    {
        float2 fx = __half22float2(*(__half2*)&xv.x), fa = __half22float2(*(__half2*)&av.x);
        o.x = pack2(fx.x + fa.x, fx.y + fa.y);
    }
    {
        float2 fx = __half22float2(*(__half2*)&xv.y), fa = __half22float2(*(__half2*)&av.y);
        o.y = pack2(fx.x + fa.x, fx.y + fa.y);
    }
    {
        float2 fx = __half22float2(*(__half2*)&xv.z), fa = __half22float2(*(__half2*)&av.z);
        o.z = pack2(fx.x + fa.x, fx.y + fa.y);
    }
    {
        float2 fx = __half22float2(*(__half2*)&xv.w), fa = __half22float2(*(__half2*)&av.w);
        o.w = pack2(fx.x + fa.x, fx.y + fa.y);
    }
    return o;
}
// swizzled byte offset within a [row][col] bf16 tile; rowb bytes per row.
__device__ __forceinline__ uint32_t swz(int r, int c, int rowb) {
    return (uint32_t)(r * rowb + ((((c >> 3) ^ (r & 7))) << 4) + (c & 7) * 2);
}
__device__ __forceinline__ void ldsm_x4(uint32_t a[4], uint32_t addr) {
    asm volatile("ldmatrix.sync.aligned.m8n8.x4.shared.b16 {%0,%1,%2,%3}, [%4];"
                 : "=r"(a[0]), "=r"(a[1]), "=r"(a[2]), "=r"(a[3]) : "r"(addr));
}
__device__ __forceinline__ void ldsm_x4_t(uint32_t a[4], uint32_t addr) {
    asm volatile("ldmatrix.sync.aligned.m8n8.x4.trans.shared.b16 {%0,%1,%2,%3}, [%4];"
                 : "=r"(a[0]), "=r"(a[1]), "=r"(a[2]), "=r"(a[3]) : "r"(addr));
}
__device__ __forceinline__ void mma_bf16(float d[4], const uint32_t a[4], uint32_t b0, uint32_t b1) {
    asm volatile("mma.sync.aligned.m16n8k16.row.col.f32.bf16.bf16.f32 "
                 "{%0,%1,%2,%3}, {%4,%5,%6,%7}, {%8,%9}, {%0,%1,%2,%3};"
                 : "+f"(d[0]), "+f"(d[1]), "+f"(d[2]), "+f"(d[3])
                 : "r"(a[0]), "r"(a[1]), "r"(a[2]), "r"(a[3]), "r"(b0), "r"(b1));
}

// ---------------- init: pool zero + fp16 bond tables + weight split blobs ----------------
__device__ __forceinline__ void split_store(unsigned char* hi, unsigned char* lo,
                                            uint32_t off, float w) {
    __nv_bfloat16 wh = __float2bfloat16_rn(w);
    __nv_bfloat16 wl = __float2bfloat16_rn(w - __bfloat162float(wh));
    *(__nv_bfloat16*)(hi + off) = wh;
    *(__nv_bfloat16*)(lo + off) = wl;
}

__global__ void k_init(const float* __restrict__ bond_emb,
                       const float* __restrict__ we0, const float* __restrict__ be0,
                       const float* __restrict__ we1, const float* __restrict__ be1,
                       const float* __restrict__ w1_0, const float* __restrict__ w2_0,
                       const float* __restrict__ w1_1, const float* __restrict__ w2_1) {
    int tid = blockIdx.x * blockDim.x + threadIdx.x;
    int nth = gridDim.x * blockDim.x;
    for (int i = tid; i < N_GRAPHS * HID; i += nth) g_pool[i] = 0.f;
    for (int i = tid; i < 16 * EMB; i += nth) {
        int bt = i >> 6, o = i & 63;
        float acc = be0[o];
        #pragma unroll 8
        for (int k = 0; k < EMB; k++) acc += bond_emb[bt * EMB + k] * we0[k * EMB + o];
        ((__half*)g_t0h)[i] = __float2half_rn(acc);
    }
    for (int i = tid; i < 16 * HID; i += nth) {
        int bt = i >> 7, o = i & 127;
        float acc = be1[o];
        #pragma unroll 8
        for (int k = 0; k < EMB; k++) acc += bond_emb[bt * EMB + k] * we1[k * HID + o];
        ((__half*)g_t1h)[i] = __float2half_rn(acc);
    }
    for (int i = tid; i < 64 * 128; i += nth) {          // L0 W1
        int k = i >> 7, n = i & 127;
        split_store(g_wb0, g_wb0 + 16384, swz(k, n, 256), w1_0[i]);
    }
    for (int i = tid; i < 128 * 128; i += nth) {         // L0 W2
        int k = i >> 7, n = i & 127;
        split_store(g_wb0 + 32768, g_wb0 + 65536, swz(k, n, 256), w2_0[i]);
    }
    for (int i = tid; i < 128 * 128; i += nth) {         // L1 W1
        int k = i >> 7, n = i & 127;
        split_store(g_wb1, g_wb1 + 32768, swz(k, n, 256), w1_1[i]);
    }
    for (int i = tid; i < 128 * 128; i += nth) {         // L1 W2
        int k = i >> 7, n = i & 127;
        split_store(g_wb1 + 65536, g_wb1 + 98304, swz(k, n, 256), w2_1[i]);
    }
}

// ---------------- gather atom embeddings (fp32 -> fp16) + zero agg0 ----------------
__global__ void k_gather(const int* __restrict__ x_idx, const float* __restrict__ atom_emb) {
    int tid = blockIdx.x * blockDim.x + threadIdx.x;
    int nth = gridDim.x * blockDim.x;
    const float4* ae = (const float4*)atom_emb;
    uint2* x0 = (uint2*)g_x0h;
    uint2* a0 = (uint2*)g_agg0h;
    const int NITEMS = N_NODES * 16;   // float4 units per node row
    for (int i = tid; i < NITEMS; i += nth) {
        int node = i >> 4;
        int c = i & 15;
        int a = x_idx[node];
        float4 v = ae[a * 16 + c];
        __half2 h0 = __floats2half2_rn(v.x, v.y);
        __half2 h1 = __floats2half2_rn(v.z, v.w);
        uint2 o;
        o.x = *(uint32_t*)&h0; o.y = *(uint32_t*)&h1;
        x0[i] = o;
        a0[i] = make_uint2(0u, 0u);
    }
}

// ---------------- edge layer 0: fp16, 4 edges per warp step (8 lanes x 16B) ----
__global__ void k_edge0(const int* __restrict__ ei, const int* __restrict__ ea) {
    __shared__ uint4 t0s[16 * 8];
    for (int i = threadIdx.x; i < 16 * 8; i += blockDim.x) t0s[i] = g_t0h[i];
    __syncthreads();
    int lane = threadIdx.x & 31;
    int wid = (blockIdx.x * blockDim.x + threadIdx.x) >> 5;
    int nw = (gridDim.x * blockDim.x) >> 5;
    int e = lane >> 3, c = lane & 7;
    const int NB = N_EDGES / 32;
    for (int b = wid; b < NB; b += nw) {
        int base = b * 32;
        int s_l = ei[base + lane];
        int d_l = ei[N_EDGES + base + lane];
        int t_l = ea[base + lane];
        #pragma unroll 4
        for (int j = 0; j < 8; j++) {
            int idx = 4 * j + e;
            int src = __shfl_sync(FULLMASK, s_l, idx);
            int dst = __shfl_sync(FULLMASK, d_l, idx);
            int bt  = __shfl_sync(FULLMASK, t_l, idx);
            uint4 v = g_x0h[src * 8 + c];
            uint4 t = t0s[bt * 8 + c];
            red_add_f16x8(&g_agg0h[dst * 8 + c], msg4(v, t));
        }
    }
}

// ---------------- edge layer 1: fp16, 2 edges per warp step (16 lanes x 16B) ----
__global__ void k_edge1(const int* __restrict__ ei, const int* __restrict__ ea) {
    __shared__ uint4 t1s[16 * 16];
    for (int i = threadIdx.x; i < 16 * 16; i += blockDim.x) t1s[i] = g_t1h[i];
    __syncthreads();
    int lane = threadIdx.x & 31;
    int wid = (blockIdx.x * blockDim.x + threadIdx.x) >> 5;
    int nw = (gridDim.x * blockDim.x) >> 5;
    int e = lane >> 4, c = lane & 15;
    const int NB = N_EDGES / 32;
    for (int b = wid; b < NB; b += nw) {
        int base = b * 32;
        int s_l = ei[base + lane];
        int d_l = ei[N_EDGES + base + lane];
        int t_l = ea[base + lane];
        #pragma unroll 4
        for (int j = 0; j < 16; j++) {
            int idx = 2 * j + e;
            int src = __shfl_sync(FULLMASK, s_l, idx);
            int dst = __shfl_sync(FULLMASK, d_l, idx);
            int bt  = __shfl_sync(FULLMASK, t_l, idx);
            uint4 v = g_x1h[src * 16 + c];
            uint4 t = t1s[bt * 16 + c];
            red_add_f16x8(&g_agg1h[dst * 16 + c], msg4(v, t));
        }
    }
}

// ============ GINE MLP on HMMA: 512 threads, 16 warps, m16 x n64 per warp ============
template<int K1, bool L1>
__global__ void __launch_bounds__(512, 1)
k_mlp_mma(const float* __restrict__ b1, const float* __restrict__ b2,
          const int* __restrict__ batch) {
    extern __shared__ char smem[];
    constexpr int W1B = K1 * 256;            // W1 buffer bytes
    constexpr int W2B = 128 * 256;           // 32768
    constexpr int RB1 = K1 * 2;              // As row bytes
    constexpr int ASB = 128 * RB1;
    constexpr int AS2B = 128 * 256;
    constexpr int BLOB = 2 * W1B + 2 * W2B;
    char* W1hi = smem;
    char* W1lo = smem + W1B;
    char* W2hi = smem + 2 * W1B;
    char* W2lo = smem + 2 * W1B + W2B;
    char* Asb  = smem + BLOB;
    char* As2b = Asb + ASB;
    float* b1s = (float*)(As2b + AS2B);
    float* b2s = b1s + 128;

    const uint4* xh = L1 ? g_x1h : g_x0h;
    const uint4* ah = L1 ? g_agg1h : g_agg0h;
    const unsigned char* blob = L1 ? g_wb1 : g_wb0;

    int tid = threadIdx.x;
    {
        const uint4* src = (const uint4*)blob;
        uint4* dst = (uint4*)smem;
        for (int i = tid; i < BLOB / 16; i += 512) dst[i] = src[i];
    }
    if (tid < 128) { b1s[tid] = b1[tid]; b2s[tid] = b2[tid]; }

    uint32_t As_u  = smem_u32(Asb);
    uint32_t As2_u = smem_u32(As2b);
    uint32_t W1hi_u = smem_u32(W1hi), W1lo_u = smem_u32(W1lo);
    uint32_t W2hi_u = smem_u32(W2hi), W2lo_u = smem_u32(W2lo);

    int lane = tid & 31, wq = tid >> 5;
    int mbase = (wq & 7) * 16;               // 16 rows per warp
    int nbase = (wq >> 3) * 64;              // 64 cols per warp
    int g = lane >> 3, lr = lane & 7;
    int fr = (g & 1) * 8 + lr;               // ldmatrix lane row-in-frag
    int fc8 = (g >> 1) * 8;                  // ldmatrix lane col-offset
    int qr = lane >> 2, qp = lane & 3;       // D-frag row/colpair

    const int NT = (N_NODES + 127) / 128;    // 782
    __syncthreads();

    for (int tile = blockIdx.x; tile < NT; tile += gridDim.x) {
        // ---- stage As: bf16(x + agg), swizzled; 4 threads/row ----
        {
            int r = tid >> 2;
            int q = tid & 3;
            int node = tile * 128 + r;
            char* rowp = Asb + r * RB1;
            constexpr int CH = K1 / 32;          // uint4 chunks per quarter
            if (node < N_NODES) {
                const uint4* xp = xh + (size_t)node * (K1 / 8) + q * CH;
                const uint4* ap = ah + (size_t)node * (K1 / 8) + q * CH;
                #pragma unroll
                for (int c = 0; c < CH; c++) {
                    int kk = q * (K1 / 4) + c * 8;
                    uint4 pk = sum_pack_bf16(xp[c], ap[c]);
                    *(uint4*)(rowp + ((((kk >> 3) ^ (r & 7))) << 4)) = pk;
                }
            } else {
                uint4 z = make_uint4(0u, 0u, 0u, 0u);
                #pragma unroll
                for (int c = 0; c < CH; c++) {
                    int kk = q * (K1 / 4) + c * 8;
                    *(uint4*)(rowp + ((((kk >> 3) ^ (r & 7))) << 4)) = z;
                }
            }
        }
        __syncthreads();

        float d0[8][4];
        #pragma unroll
        for (int i = 0; i < 8; i++)
            #pragma unroll
            for (int j = 0; j < 4; j++) d0[i][j] = 0.f;

        // ---- GEMM1: A[128xK1] @ W1 ----
        #pragma unroll
        for (int ks = 0; ks < K1 / 16; ks++) {
            uint32_t a0[4];
            ldsm_x4(a0, As_u + swz(mbase + fr, ks * 16 + fc8, RB1));
            #pragma unroll
            for (int np = 0; np < 4; np++) {
                uint32_t woff = swz(ks * 16 + fr, nbase + np * 16 + fc8, 256);
                uint32_t bh[4], bl[4];
                ldsm_x4_t(bh, W1hi_u + woff);
                mma_bf16(d0[2 * np], a0, bh[0], bh[1]); mma_bf16(d0[2 * np + 1], a0, bh[2], bh[3]);
                ldsm_x4_t(bl, W1lo_u + woff);
                mma_bf16(d0[2 * np], a0, bl[0], bl[1]); mma_bf16(d0[2 * np + 1], a0, bl[2], bl[3]);
            }
        }

        // ---- epilogue1: t = elu(D + b1) -> As2 (bf16, swizzled) ----
        #pragma unroll
        for (int i = 0; i < 8; i++) {
            int n = nbase + i * 8 + qp * 2;
            float bb0 = b1s[n], bb1 = b1s[n + 1];
            *(uint32_t*)(As2b + swz(mbase + qr,     n, 256)) = pack2(elu_fast(d0[i][0] + bb0), elu_fast(d0[i][1] + bb1));
            *(uint32_t*)(As2b + swz(mbase + qr + 8, n, 256)) = pack2(elu_fast(d0[i][2] + bb0), elu_fast(d0[i][3] + bb1));
        }
        __syncthreads();

        #pragma unroll
        for (int i = 0; i < 8; i++)
            #pragma unroll
            for (int j = 0; j < 4; j++) d0[i][j] = 0.f;

        // ---- GEMM2: t[128x128] @ W2 ----
        #pragma unroll
        for (int ks = 0; ks < 8; ks++) {
            uint32_t a0[4];
            ldsm_x4(a0, As2_u + swz(mbase + fr, ks * 16 + fc8, 256));
            #pragma unroll
            for (int np = 0; np < 4; np++) {
                uint32_t woff = swz(ks * 16 + fr, nbase + np * 16 + fc8, 256);
                uint32_t bh[4], bl[4];
                ldsm_x4_t(bh, W2hi_u + woff);
                mma_bf16(d0[2 * np], a0, bh[0], bh[1]); mma_bf16(d0[2 * np + 1], a0, bh[2], bh[3]);
                ldsm_x4_t(bl, W2lo_u + woff);
                mma_bf16(d0[2 * np], a0, bl[0], bl[1]); mma_bf16(d0[2 * np + 1], a0, bl[2], bl[3]);
            }
        }

        // ---- epilogue2 ----
        if constexpr (!L1) {
            #pragma unroll
            for (int f = 0; f < 2; f++) {
                int row = mbase + qr + f * 8;
                int node = tile * 128 + row;
                if (node < N_NODES) {
                    uint32_t* xo = (uint32_t*)g_x1h + (size_t)node * 64;
                    uint32_t* ao = (uint32_t*)g_agg1h + (size_t)node * 64;
                    #pragma unroll
                    for (int i = 0; i < 8; i++) {
                        int n = nbase + i * 8 + qp * 2;
                        float o0 = elu_fast(d0[i][2 * f]     + b2s[n]);
                        float o1 = elu_fast(d0[i][2 * f + 1] + b2s[n + 1]);
                        __half2 h = __floats2half2_rn(o0, o1);
                        xo[n >> 1] = *(uint32_t*)&h;
                        ao[n >> 1] = 0u;
                    }
                }
            }
        } else {
            #pragma unroll
            for (int f = 0; f < 2; f++) {
                int row = mbase + qr + f * 8;
                int node = tile * 128 + row;
                if (node < N_NODES) {
                    int gg = batch[node];
                    float* pp = g_pool + (size_t)gg * HID;
                    #pragma unroll
                    for (int i = 0; i < 8; i++) {
                        int n = nbase + i * 8 + qp * 2;
                        float o0 = elu_fast(d0[i][2 * f]     + b2s[n]);
                        float o1 = elu_fast(d0[i][2 * f + 1] + b2s[n + 1]);
                        red_add_v2(pp + n, o0, o1);
                    }
                }
            }
        }
        __syncthreads();
    }
}

// ---------------- head ----------------
__global__ void k_head(const float* __restrict__ w1, const float* __restrict__ b1,
                       const float* __restrict__ w2, const float* __restrict__ b2,
                       float* __restrict__ out) {
    __shared__ float p_s[HID], h_s[HID];
    int g = blockIdx.x, t = threadIdx.x;
    p_s[t] = g_pool[g * HID + t];
    __syncthreads();
    float acc = b1[t];
    #pragma unroll 8
    for (int k = 0; k < HID; k++) acc += p_s[k] * w1[k * N_TASKS + t];
    h_s[t] = fmaxf(acc, 0.f);
    __syncthreads();
    acc = b2[t];
    #pragma unroll 8
    for (int k = 0; k < HID; k++) acc += h_s[k] * w2[k * N_TASKS + t];
    out[g * N_TASKS + t] = acc;
}

// ---------------- launch ----------------
extern "C" void kernel_launch(void* const* d_in, const int* in_sizes, int n_in,
                              void* d_out, int out_size) {
    const int*   x_idx    = (const int*)  d_in[0];
    const int*   ei       = (const int*)  d_in[1];
    const int*   ea       = (const int*)  d_in[2];
    const int*   batch    = (const int*)  d_in[3];
    const float* atom_emb = (const float*)d_in[4];
    const float* bond_emb = (const float*)d_in[5];
    const float* we0      = (const float*)d_in[6];
    const float* be0      = (const float*)d_in[7];
    const float* w1_0     = (const float*)d_in[8];
    const float* b1_0     = (const float*)d_in[9];
    const float* w2_0     = (const float*)d_in[10];
    const float* b2_0     = (const float*)d_in[11];
    const float* we1      = (const float*)d_in[12];
    const float* be1      = (const float*)d_in[13];
    const float* w1_1     = (const float*)d_in[14];
    const float* b1_1     = (const float*)d_in[15];
    const float* w2_1     = (const float*)d_in[16];
    const float* b2_1     = (const float*)d_in[17];
    const float* lin1_w   = (const float*)d_in[18];
    const float* lin1_b   = (const float*)d_in[19];
    const float* lin2_w   = (const float*)d_in[20];
    const float* lin2_b   = (const float*)d_in[21];
    float* out = (float*)d_out;

    int smem0 = 98304  + 16384 + 32768 + 1024;   // 148480
    int smem1 = 131072 + 32768 + 32768 + 1024;   // 197632
    cudaFuncSetAttribute(k_mlp_mma<64, false>, cudaFuncAttributeMaxDynamicSharedMemorySize, smem0);
    cudaFuncSetAttribute(k_mlp_mma<128, true>, cudaFuncAttributeMaxDynamicSharedMemorySize, smem1);

    k_init  <<<128, 256>>>(bond_emb, we0, be0, we1, be1, w1_0, w2_0, w1_1, w2_1);
    k_gather<<<2048, 256>>>(x_idx, atom_emb);
    k_edge0 <<<1480, 256>>>(ei, ea);
    k_mlp_mma<64, false><<<148, 512, smem0>>>(b1_0, b2_0, batch);
    k_edge1 <<<1480, 256>>>(ei, ea);
    k_mlp_mma<128, true><<<148, 512, smem1>>>(b1_1, b2_1, batch);
    k_head  <<<512, 128>>>(lin1_w, lin1_b, lin2_w, lin2_b, out);
}

// round 7
// speedup vs baseline: 2.6776x; 1.1400x over previous
#include <cuda_runtime.h>
#include <cuda_bf16.h>
#include <cuda_fp16.h>
#include <cstdint>

#define N_NODES 100000
#define N_EDGES 1600000
#define EMB 64
#define HID 128
#define N_GRAPHS 512
#define N_TASKS 128
#define FULLMASK 0xffffffffu

// ---------------- device scratch (static, no allocation) ----------------
__device__ __align__(16) uint4 g_x0h[N_NODES * 8];     // 64 halves per node
__device__ __align__(16) uint4 g_agg0h[N_NODES * 8];
__device__ __align__(16) uint4 g_x1h[N_NODES * 16];    // 128 halves per node
__device__ __align__(16) uint4 g_agg1h[N_NODES * 16];
__device__ __align__(16) uint4 g_t0h[16 * 8];          // bond table L0 (fp16)
__device__ __align__(16) uint4 g_t1h[16 * 16];         // bond table L1 (fp16)
__device__ __align__(16) float g_pool[N_GRAPHS * HID];
// fp16 weights, pre-swizzled to match smem layout exactly:
// layer0: [W1 16384 | W2 32768]   layer1: [W1 32768 | W2 32768]
__device__ __align__(16) unsigned char g_wb0[49152];
__device__ __align__(16) unsigned char g_wb1[65536];

// ---------------- helpers ----------------
__device__ __forceinline__ void red_add_v2(float* p, float a, float b) {
    asm volatile("red.global.add.v2.f32 [%0], {%1,%2};"
                 :: "l"(p), "f"(a), "f"(b) : "memory");
}
__device__ __forceinline__ void red_add_f16x8(uint4* p, uint4 v) {
    asm volatile("red.global.add.noftz.v4.f16x2 [%0], {%1,%2,%3,%4};"
                 :: "l"(p), "r"(v.x), "r"(v.y), "r"(v.z), "r"(v.w) : "memory");
}
__device__ __forceinline__ float elu_fast(float x) { return x > 0.f ? x : (__expf(x) - 1.f); }
__device__ __forceinline__ uint32_t smem_u32(const void* p) {
    uint32_t a;
    asm("{ .reg .u64 t; cvta.to.shared.u64 t, %1; cvt.u32.u64 %0, t; }" : "=r"(a) : "l"(p));
    return a;
}
// half2 relu(a+b)
__device__ __forceinline__ uint32_t h2ra(uint32_t a, uint32_t b) {
    __half2 s = __hadd2(*(__half2*)&a, *(__half2*)&b);
    __half2 z = __float2half2_rn(0.f);
    s = __hmax2(s, z);
    return *(uint32_t*)&s;
}
__device__ __forceinline__ uint4 msg4(uint4 v, uint4 t) {
    uint4 m;
    m.x = h2ra(v.x, t.x); m.y = h2ra(v.y, t.y);
    m.z = h2ra(v.z, t.z); m.w = h2ra(v.w, t.w);
    return m;
}
// fp16 x + fp16 agg (8 halves)
__device__ __forceinline__ uint32_t h2a(uint32_t a, uint32_t b) {
    __half2 s = __hadd2(*(__half2*)&a, *(__half2*)&b);
    return *(uint32_t*)&s;
}
__device__ __forceinline__ uint4 hadd2x4(uint4 a, uint4 b) {
    uint4 o;
    o.x = h2a(a.x, b.x); o.y = h2a(a.y, b.y);
    o.z = h2a(a.z, b.z); o.w = h2a(a.w, b.w);
    return o;
}
__device__ __forceinline__ uint32_t packh2(float a, float b) {
    __half2 h = __floats2half2_rn(a, b);
    return *(uint32_t*)&h;
}
// swizzled byte offset within a [row][col] 16-bit-element tile; rowb bytes per row.
__device__ __forceinline__ uint32_t swz(int r, int c, int rowb) {
    return (uint32_t)(r * rowb + ((((c >> 3) ^ (r & 7))) << 4) + (c & 7) * 2);
}
__device__ __forceinline__ void ldsm_x4(uint32_t a[4], uint32_t addr) {
    asm volatile("ldmatrix.sync.aligned.m8n8.x4.shared.b16 {%0,%1,%2,%3}, [%4];"
                 : "=r"(a[0]), "=r"(a[1]), "=r"(a[2]), "=r"(a[3]) : "r"(addr));
}
__device__ __forceinline__ void ldsm_x4_t(uint32_t a[4], uint32_t addr) {
    asm volatile("ldmatrix.sync.aligned.m8n8.x4.trans.shared.b16 {%0,%1,%2,%3}, [%4];"
                 : "=r"(a[0]), "=r"(a[1]), "=r"(a[2]), "=r"(a[3]) : "r"(addr));
}
__device__ __forceinline__ void mma_fp16(float d[4], const uint32_t a[4], uint32_t b0, uint32_t b1) {
    asm volatile("mma.sync.aligned.m16n8k16.row.col.f32.f16.f16.f32 "
                 "{%0,%1,%2,%3}, {%4,%5,%6,%7}, {%8,%9}, {%0,%1,%2,%3};"
                 : "+f"(d[0]), "+f"(d[1]), "+f"(d[2]), "+f"(d[3])
                 : "r"(a[0]), "r"(a[1]), "r"(a[2]), "r"(a[3]), "r"(b0), "r"(b1));
}

// ---------------- init: pool zero + fp16 bond tables + fp16 weight blobs ----------------
__global__ void k_init(const float* __restrict__ bond_emb,
                       const float* __restrict__ we0, const float* __restrict__ be0,
                       const float* __restrict__ we1, const float* __restrict__ be1,
                       const float* __restrict__ w1_0, const float* __restrict__ w2_0,
                       const float* __restrict__ w1_1, const float* __restrict__ w2_1) {
    int tid = blockIdx.x * blockDim.x + threadIdx.x;
    int nth = gridDim.x * blockDim.x;
    for (int i = tid; i < N_GRAPHS * HID; i += nth) g_pool[i] = 0.f;
    for (int i = tid; i < 16 * EMB; i += nth) {
        int bt = i >> 6, o = i & 63;
        float acc = be0[o];
        #pragma unroll 8
        for (int k = 0; k < EMB; k++) acc += bond_emb[bt * EMB + k] * we0[k * EMB + o];
        ((__half*)g_t0h)[i] = __float2half_rn(acc);
    }
    for (int i = tid; i < 16 * HID; i += nth) {
        int bt = i >> 7, o = i & 127;
        float acc = be1[o];
        #pragma unroll 8
        for (int k = 0; k < EMB; k++) acc += bond_emb[bt * EMB + k] * we1[k * HID + o];
        ((__half*)g_t1h)[i] = __float2half_rn(acc);
    }
    for (int i = tid; i < 64 * 128; i += nth) {          // L0 W1
        int k = i >> 7, n = i & 127;
        *(__half*)(g_wb0 + swz(k, n, 256)) = __float2half_rn(w1_0[i]);
    }
    for (int i = tid; i < 128 * 128; i += nth) {         // L0 W2
        int k = i >> 7, n = i & 127;
        *(__half*)(g_wb0 + 16384 + swz(k, n, 256)) = __float2half_rn(w2_0[i]);
    }
    for (int i = tid; i < 128 * 128; i += nth) {         // L1 W1
        int k = i >> 7, n = i & 127;
        *(__half*)(g_wb1 + swz(k, n, 256)) = __float2half_rn(w1_1[i]);
    }
    for (int i = tid; i < 128 * 128; i += nth) {         // L1 W2
        int k = i >> 7, n = i & 127;
        *(__half*)(g_wb1 + 32768 + swz(k, n, 256)) = __float2half_rn(w2_1[i]);
    }
}

// ---------------- gather atom embeddings (fp32 -> fp16) + zero agg0 ----------------
__global__ void k_gather(const int* __restrict__ x_idx, const float* __restrict__ atom_emb) {
    int tid = blockIdx.x * blockDim.x + threadIdx.x;
    int nth = gridDim.x * blockDim.x;
    const float4* ae = (const float4*)atom_emb;
    uint2* x0 = (uint2*)g_x0h;
    uint2* a0 = (uint2*)g_agg0h;
    const int NITEMS = N_NODES * 16;
    for (int i = tid; i < NITEMS; i += nth) {
        int node = i >> 4;
        int c = i & 15;
        int a = x_idx[node];
        float4 v = ae[a * 16 + c];
        uint2 o;
        o.x = packh2(v.x, v.y); o.y = packh2(v.z, v.w);
        x0[i] = o;
        a0[i] = make_uint2(0u, 0u);
    }
}

// ---------------- edge layer 0: fp16, 4 edges per warp step ----------------
__global__ void k_edge0(const int* __restrict__ ei, const int* __restrict__ ea) {
    __shared__ uint4 t0s[16 * 8];
    for (int i = threadIdx.x; i < 16 * 8; i += blockDim.x) t0s[i] = g_t0h[i];
    __syncthreads();
    int lane = threadIdx.x & 31;
    int wid = (blockIdx.x * blockDim.x + threadIdx.x) >> 5;
    int nw = (gridDim.x * blockDim.x) >> 5;
    int e = lane >> 3, c = lane & 7;
    const int NB = N_EDGES / 32;
    for (int b = wid; b < NB; b += nw) {
        int base = b * 32;
        int s_l = ei[base + lane];
        int d_l = ei[N_EDGES + base + lane];
        int t_l = ea[base + lane];
        #pragma unroll 4
        for (int j = 0; j < 8; j++) {
            int idx = 4 * j + e;
            int src = __shfl_sync(FULLMASK, s_l, idx);
            int dst = __shfl_sync(FULLMASK, d_l, idx);
            int bt  = __shfl_sync(FULLMASK, t_l, idx);
            uint4 v = g_x0h[src * 8 + c];
            uint4 t = t0s[bt * 8 + c];
            red_add_f16x8(&g_agg0h[dst * 8 + c], msg4(v, t));
        }
    }
}

// ---------------- edge layer 1: fp16, 2 edges per warp step ----------------
__global__ void k_edge1(const int* __restrict__ ei, const int* __restrict__ ea) {
    __shared__ uint4 t1s[16 * 16];
    for (int i = threadIdx.x; i < 16 * 16; i += blockDim.x) t1s[i] = g_t1h[i];
    __syncthreads();
    int lane = threadIdx.x & 31;
    int wid = (blockIdx.x * blockDim.x + threadIdx.x) >> 5;
    int nw = (gridDim.x * blockDim.x) >> 5;
    int e = lane >> 4, c = lane & 15;
    const int NB = N_EDGES / 32;
    for (int b = wid; b < NB; b += nw) {
        int base = b * 32;
        int s_l = ei[base + lane];
        int d_l = ei[N_EDGES + base + lane];
        int t_l = ea[base + lane];
        #pragma unroll 4
        for (int j = 0; j < 16; j++) {
            int idx = 2 * j + e;
            int src = __shfl_sync(FULLMASK, s_l, idx);
            int dst = __shfl_sync(FULLMASK, d_l, idx);
            int bt  = __shfl_sync(FULLMASK, t_l, idx);
            uint4 v = g_x1h[src * 16 + c];
            uint4 t = t1s[bt * 16 + c];
            red_add_f16x8(&g_agg1h[dst * 16 + c], msg4(v, t));
        }
    }
}

// ============ GINE MLP on HMMA fp16: 1024 threads, 32 warps, m16 x n32 per warp ============
template<int K1, bool L1>
__global__ void __launch_bounds__(1024, 1)
k_mlp_mma(const float* __restrict__ b1, const float* __restrict__ b2,
          const int* __restrict__ batch) {
    extern __shared__ char smem[];
    constexpr int W1B = K1 * 256;            // W1 bytes
    constexpr int W2B = 128 * 256;           // 32768
    constexpr int RB1 = K1 * 2;              // As row bytes
    constexpr int ASB = 128 * RB1;
    constexpr int AS2B = 128 * 256;
    constexpr int BLOB = W1B + W2B;
    char* W1s  = smem;
    char* W2s  = smem + W1B;
    char* Asb  = smem + BLOB;
    char* As2b = Asb + ASB;
    float* b1s = (float*)(As2b + AS2B);
    float* b2s = b1s + 128;

    const uint4* xh = L1 ? g_x1h : g_x0h;
    const uint4* ah = L1 ? g_agg1h : g_agg0h;
    const unsigned char* blob = L1 ? g_wb1 : g_wb0;

    int tid = threadIdx.x;
    {
        const uint4* src = (const uint4*)blob;
        uint4* dst = (uint4*)smem;
        for (int i = tid; i < BLOB / 16; i += 1024) dst[i] = src[i];
    }
    if (tid < 128) { b1s[tid] = b1[tid]; b2s[tid] = b2[tid]; }

    uint32_t As_u  = smem_u32(Asb);
    uint32_t As2_u = smem_u32(As2b);
    uint32_t W1_u  = smem_u32(W1s);
    uint32_t W2_u  = smem_u32(W2s);

    int lane = tid & 31, wq = tid >> 5;
    int mbase = (wq & 7) * 16;               // 8 m-groups of 16 rows
    int nbase = (wq >> 3) * 32;              // 4 n-groups of 32 cols
    int g = lane >> 3, lr = lane & 7;
    int fr = (g & 1) * 8 + lr;               // ldmatrix lane row-in-frag
    int fc8 = (g >> 1) * 8;                  // ldmatrix lane col-offset
    int qr = lane >> 2, qp = lane & 3;       // D-frag row/colpair

    const int NT = (N_NODES + 127) / 128;    // 782
    __syncthreads();

    for (int tile = blockIdx.x; tile < NT; tile += gridDim.x) {
        // ---- stage As: fp16 (x + agg), swizzled; 8 threads/row ----
        {
            int r = tid >> 3;
            int q = tid & 7;
            int node = tile * 128 + r;
            char* rowp = Asb + r * RB1;
            constexpr int CH = K1 / 64;          // uint4 chunks per thread (1 or 2)
            if (node < N_NODES) {
                const uint4* xp = xh + (size_t)node * (K1 / 8) + q * CH;
                const uint4* ap = ah + (size_t)node * (K1 / 8) + q * CH;
                #pragma unroll
                for (int c = 0; c < CH; c++) {
                    int kk = (q * CH + c) * 8;
                    uint4 pk = hadd2x4(xp[c], ap[c]);
                    *(uint4*)(rowp + ((((kk >> 3) ^ (r & 7))) << 4)) = pk;
                }
            } else {
                uint4 z = make_uint4(0u, 0u, 0u, 0u);
                #pragma unroll
                for (int c = 0; c < CH; c++) {
                    int kk = (q * CH + c) * 8;
                    *(uint4*)(rowp + ((((kk >> 3) ^ (r & 7))) << 4)) = z;
                }
            }
        }
        __syncthreads();

        float d0[4][4];
        #pragma unroll
        for (int i = 0; i < 4; i++)
            #pragma unroll
            for (int j = 0; j < 4; j++) d0[i][j] = 0.f;

        // ---- GEMM1: A[128xK1] @ W1 ----
        #pragma unroll
        for (int ks = 0; ks < K1 / 16; ks++) {
            uint32_t a0[4];
            ldsm_x4(a0, As_u + swz(mbase + fr, ks * 16 + fc8, RB1));
            #pragma unroll
            for (int np = 0; np < 2; np++) {
                uint32_t bh[4];
                ldsm_x4_t(bh, W1_u + swz(ks * 16 + fr, nbase + np * 16 + fc8, 256));
                mma_fp16(d0[2 * np], a0, bh[0], bh[1]);
                mma_fp16(d0[2 * np + 1], a0, bh[2], bh[3]);
            }
        }

        // ---- epilogue1: t = elu(D + b1) -> As2 (fp16, swizzled) ----
        #pragma unroll
        for (int i = 0; i < 4; i++) {
            int n = nbase + i * 8 + qp * 2;
            float bb0 = b1s[n], bb1 = b1s[n + 1];
            *(uint32_t*)(As2b + swz(mbase + qr,     n, 256)) = packh2(elu_fast(d0[i][0] + bb0), elu_fast(d0[i][1] + bb1));
            *(uint32_t*)(As2b + swz(mbase + qr + 8, n, 256)) = packh2(elu_fast(d0[i][2] + bb0), elu_fast(d0[i][3] + bb1));
        }
        __syncthreads();

        #pragma unroll
        for (int i = 0; i < 4; i++)
            #pragma unroll
            for (int j = 0; j < 4; j++) d0[i][j] = 0.f;

        // ---- GEMM2: t[128x128] @ W2 ----
        #pragma unroll
        for (int ks = 0; ks < 8; ks++) {
            uint32_t a0[4];
            ldsm_x4(a0, As2_u + swz(mbase + fr, ks * 16 + fc8, 256));
            #pragma unroll
            for (int np = 0; np < 2; np++) {
                uint32_t bh[4];
                ldsm_x4_t(bh, W2_u + swz(ks * 16 + fr, nbase + np * 16 + fc8, 256));
                mma_fp16(d0[2 * np], a0, bh[0], bh[1]);
                mma_fp16(d0[2 * np + 1], a0, bh[2], bh[3]);
            }
        }

        // ---- epilogue2 ----
        if constexpr (!L1) {
            #pragma unroll
            for (int f = 0; f < 2; f++) {
                int row = mbase + qr + f * 8;
                int node = tile * 128 + row;
                if (node < N_NODES) {
                    uint32_t* xo = (uint32_t*)g_x1h + (size_t)node * 64;
                    uint32_t* ao = (uint32_t*)g_agg1h + (size_t)node * 64;
                    #pragma unroll
                    for (int i = 0; i < 4; i++) {
                        int n = nbase + i * 8 + qp * 2;
                        float o0 = elu_fast(d0[i][2 * f]     + b2s[n]);
                        float o1 = elu_fast(d0[i][2 * f + 1] + b2s[n + 1]);
                        xo[n >> 1] = packh2(o0, o1);
                        ao[n >> 1] = 0u;
                    }
                }
            }
        } else {
            #pragma unroll
            for (int f = 0; f < 2; f++) {
                int row = mbase + qr + f * 8;
                int node = tile * 128 + row;
                if (node < N_NODES) {
                    int gg = batch[node];
                    float* pp = g_pool + (size_t)gg * HID;
                    #pragma unroll
                    for (int i = 0; i < 4; i++) {
                        int n = nbase + i * 8 + qp * 2;
                        float o0 = elu_fast(d0[i][2 * f]     + b2s[n]);
                        float o1 = elu_fast(d0[i][2 * f + 1] + b2s[n + 1]);
                        red_add_v2(pp + n, o0, o1);
                    }
                }
            }
        }
        __syncthreads();
    }
}

// ---------------- head ----------------
__global__ void k_head(const float* __restrict__ w1, const float* __restrict__ b1,
                       const float* __restrict__ w2, const float* __restrict__ b2,
                       float* __restrict__ out) {
    __shared__ float p_s[HID], h_s[HID];
    int g = blockIdx.x, t = threadIdx.x;
    p_s[t] = g_pool[g * HID + t];
    __syncthreads();
    float acc = b1[t];
    #pragma unroll 8
    for (int k = 0; k < HID; k++) acc += p_s[k] * w1[k * N_TASKS + t];
    h_s[t] = fmaxf(acc, 0.f);
    __syncthreads();
    acc = b2[t];
    #pragma unroll 8
    for (int k = 0; k < HID; k++) acc += h_s[k] * w2[k * N_TASKS + t];
    out[g * N_TASKS + t] = acc;
}

// ---------------- launch ----------------
extern "C" void kernel_launch(void* const* d_in, const int* in_sizes, int n_in,
                              void* d_out, int out_size) {
    const int*   x_idx    = (const int*)  d_in[0];
    const int*   ei       = (const int*)  d_in[1];
    const int*   ea       = (const int*)  d_in[2];
    const int*   batch    = (const int*)  d_in[3];
    const float* atom_emb = (const float*)d_in[4];
    const float* bond_emb = (const float*)d_in[5];
    const float* we0      = (const float*)d_in[6];
    const float* be0      = (const float*)d_in[7];
    const float* w1_0     = (const float*)d_in[8];
    const float* b1_0     = (const float*)d_in[9];
    const float* w2_0     = (const float*)d_in[10];
    const float* b2_0     = (const float*)d_in[11];
    const float* we1      = (const float*)d_in[12];
    const float* be1      = (const float*)d_in[13];
    const float* w1_1     = (const float*)d_in[14];
    const float* b1_1     = (const float*)d_in[15];
    const float* w2_1     = (const float*)d_in[16];
    const float* b2_1     = (const float*)d_in[17];
    const float* lin1_w   = (const float*)d_in[18];
    const float* lin1_b   = (const float*)d_in[19];
    const float* lin2_w   = (const float*)d_in[20];
    const float* lin2_b   = (const float*)d_in[21];
    float* out = (float*)d_out;

    // smem: W1 + W2 + As + As2 + biases
    int smem0 = 16384 + 32768 + 16384 + 32768 + 1024;   //  99328
    int smem1 = 32768 + 32768 + 32768 + 32768 + 1024;   // 132096
    cudaFuncSetAttribute(k_mlp_mma<64, false>, cudaFuncAttributeMaxDynamicSharedMemorySize, smem0);
    cudaFuncSetAttribute(k_mlp_mma<128, true>, cudaFuncAttributeMaxDynamicSharedMemorySize, smem1);

    k_init  <<<128, 256>>>(bond_emb, we0, be0, we1, be1, w1_0, w2_0, w1_1, w2_1);
    k_gather<<<2048, 256>>>(x_idx, atom_emb);
    k_edge0 <<<1480, 256>>>(ei, ea);
    k_mlp_mma<64, false><<<148, 1024, smem0>>>(b1_0, b2_0, batch);
    k_edge1 <<<1480, 256>>>(ei, ea);
    k_mlp_mma<128, true><<<148, 1024, smem1>>>(b1_1, b2_1, batch);
    k_head  <<<512, 128>>>(lin1_w, lin1_b, lin2_w, lin2_b, out);
}